// round 8
// baseline (speedup 1.0000x reference)
#include <cuda_runtime.h>
#include <cfloat>
#include <math.h>

#define FULL 0xffffffffu

constexpr int B = 4;
constexpr int N = 8192;
constexpr int M = 4096;
constexpr int F = 64;
constexpr int K = 16;
constexpr float MIN_SIGMA = 1e-4f;

constexpr int   NB    = 128;      // x-bins
constexpr float XLO   = -3.2f;
constexpr float XW    = 0.05f;
constexpr float XINVW = 20.0f;
constexpr float EPSP  = 1e-4f;    // conservative pad on bin-edge gaps

// Scratch (no allocations allowed)
__device__ float  g_featT[(size_t)B * N * F];   // (B,N,F) transposed features
__device__ float4 g_sorted[B * N];              // points {x,y,z,bits(n)}, x-bin-sorted
__device__ float4 g_qsorted[B * M];             // queries {x,y,z,bits(m)}, x-bin-sorted
__device__ int    g_start[B * (NB + 1)];        // point bin offsets
__device__ int    g_task[B];                    // dynamic task counters

// ---------------------------------------------------------------------------
__device__ __forceinline__ int xbin(float x) {
    return min(NB - 1, max(0, (int)floorf((x - XLO) * XINVW)));
}

// ---------------------------------------------------------------------------
// Fused build: one CTA per (kind, batch). smem histogram + warp scan +
// smem-cursor scatter. Also zeroes the task counters for this replay.
// ---------------------------------------------------------------------------
__global__ void __launch_bounds__(1024, 1)
build_kernel(const float* __restrict__ pc, const float* __restrict__ qc) {
    __shared__ int cnt[NB];
    __shared__ int cur[NB];
    const int g = blockIdx.x;            // 0..3: points, 4..7: queries
    const bool isQ = g >= B;
    const int b = isQ ? g - B : g;
    const int n = isQ ? M : N;
    const float* src = isQ ? qc + (size_t)b * 3 * M : pc + (size_t)b * 3 * N;
    float4* dst = isQ ? g_qsorted + (size_t)b * M : g_sorted + (size_t)b * N;
    const int tid = threadIdx.x;

    if (g == 0 && tid < B) g_task[tid] = 0;

    for (int i = tid; i < NB; i += blockDim.x) cnt[i] = 0;
    __syncthreads();
    for (int i = tid; i < n; i += blockDim.x)
        atomicAdd(&cnt[xbin(src[i])], 1);
    __syncthreads();
    if (tid < 32) {   // warp 0: exclusive scan of 128 bins, 4 per lane
        const int lane = tid;
        const int o = lane * 4;
        int v0 = cnt[o], v1 = cnt[o + 1], v2 = cnt[o + 2], v3 = cnt[o + 3];
        const int tsum = v0 + v1 + v2 + v3;
        int inc = tsum;
        #pragma unroll
        for (int off = 1; off < 32; off <<= 1) {
            int nb = __shfl_up_sync(FULL, inc, off);
            if (lane >= off) inc += nb;
        }
        int acc = inc - tsum;
        cur[o] = acc;
        if (!isQ) g_start[b * (NB + 1) + o] = acc;
        acc += v0;
        cur[o + 1] = acc;
        if (!isQ) g_start[b * (NB + 1) + o + 1] = acc;
        acc += v1;
        cur[o + 2] = acc;
        if (!isQ) g_start[b * (NB + 1) + o + 2] = acc;
        acc += v2;
        cur[o + 3] = acc;
        if (!isQ) g_start[b * (NB + 1) + o + 3] = acc;
        acc += v3;
        if (!isQ && lane == 31) g_start[b * (NB + 1) + NB] = acc;
    }
    __syncthreads();
    for (int i = tid; i < n; i += blockDim.x) {
        const float x = src[i], y = src[n + i], z = src[2 * n + i];
        const int pos = atomicAdd(&cur[xbin(x)], 1);
        dst[pos] = make_float4(x, y, z, __int_as_float(i));
    }
}

// ---------------------------------------------------------------------------
__global__ void transpose_feat_kernel(const float* __restrict__ feat) {
    __shared__ float tile[32][33];
    const int b  = blockIdx.z;
    const int n0 = blockIdx.x * 32;
    const int f0 = blockIdx.y * 32;
    const int tx = threadIdx.x, ty = threadIdx.y;
    #pragma unroll
    for (int i = ty; i < 32; i += 8)
        tile[i][tx] = feat[(size_t)b * F * N + (size_t)(f0 + i) * N + (n0 + tx)];
    __syncthreads();
    #pragma unroll
    for (int i = ty; i < 32; i += 8)
        g_featT[((size_t)b * N + (n0 + i)) * F + (f0 + tx)] = tile[tx][i];
}

// ---------------------------------------------------------------------------
// Warp-cooperative top-K insert into sorted 16-entry list held in lanes
// [base, base+16); candidates from any lane; threshold warp-uniform.
// ---------------------------------------------------------------------------
__device__ __forceinline__ void topk_insert(float s, int pidx, int lane,
                                            float& val, int& idx,
                                            float& threshold, int base) {
    unsigned bal = __ballot_sync(FULL, s < threshold);
    while (bal) {
        const int src = __ffs(bal) - 1;
        bal &= bal - 1;
        const float cs = __shfl_sync(FULL, s, src);
        if (cs < threshold) {
            const int ci = __shfl_sync(FULL, pidx, src);
            const bool mine = (unsigned)(lane - base) < (unsigned)K;
            const unsigned less = __ballot_sync(FULL, mine && (val <= cs));
            const int pos = base + __popc(less);
            const float ot = __shfl_up_sync(FULL, val, 1);
            const int   oi = __shfl_up_sync(FULL, idx, 1);
            if (mine) {
                if (lane == pos)     { val = cs; idx = ci; }
                else if (lane > pos) { val = ot; idx = oi; }
            }
            threshold = __shfl_sync(FULL, val, base + K - 1);
        }
    }
}

// ---------------------------------------------------------------------------
// Query kernel: one warp handles TWO x-adjacent queries per dynamic task.
// Seed: 128 array-adjacent points folded in with dual bitonic sort+merge
// (fixed latency, no serial inserts). Then bin-wise dynamic-boundary scan
// with serial inserts for the (now rare) remaining candidates.
// ---------------------------------------------------------------------------
__global__ void __launch_bounds__(1024, 1)
soft_projection_query(const float* __restrict__ temp,
                      float* __restrict__ out) {
    extern __shared__ char smraw[];
    float4* spts = (float4*)smraw;                                // 128KB
    int*   cst = (int*)(smraw + (size_t)N * sizeof(float4));      // NB+1 ints
    float* stw = (float*)(smraw + (size_t)N * sizeof(float4) + 512 + 4);  // 32w x 32 f
    int*   sti = (int*)  (smraw + (size_t)N * sizeof(float4) + 512 + 4 + 4096);

    const int b = blockIdx.y;
    for (int i = threadIdx.x; i < N; i += blockDim.x) spts[i] = g_sorted[b * N + i];
    for (int i = threadIdx.x; i < NB + 1; i += blockDim.x)
        cst[i] = g_start[b * (NB + 1) + i];
    __syncthreads();

    const float t = *temp;
    const float inv_sigma = 1.0f / fmaxf(t * t, MIN_SIGMA);

    const int lane = threadIdx.x & 31;
    const int warp = threadIdx.x >> 5;
    float* mysw = stw + warp * 32;
    int*   mysi = sti + warp * 32;

    float* out_pts  = out + (size_t)b * 3 * M;
    float* out_feat = out + (size_t)B * 3 * M + (size_t)b * F * M;
    const float* featb = g_featT + (size_t)b * N * F;
    const float4* qs = g_qsorted + (size_t)b * M;

    constexpr int NT = M / 2;         // 2048 tasks per batch
    while (true) {
        int pos;
        if (lane == 0) pos = atomicAdd(&g_task[b], 1);
        pos = __shfl_sync(FULL, pos, 0);
        if (pos >= NT) break;
        // center-out order (longest tasks first)
        const int task = (NT / 2) + ((pos & 1) ? -((pos + 1) >> 1) : (pos >> 1));

        const float4 QA = qs[2 * task];
        const float4 QB = qs[2 * task + 1];
        const int mA = __float_as_int(QA.w);
        const int mB = __float_as_int(QB.w);

        float val, thA, thB;
        int   idx;

        // ---- seed: 128 array-adjacent points, bitonic init + 3 merges ----
        const int h = xbin(0.5f * (QA.x + QB.x));
        const int c = (cst[h] + cst[h + 1]) >> 1;
        const int s0 = min(max(c - 64, 0), N - 128);
        {
            // init chunk
            {
                const float4 pt = spts[s0 + lane];
                const float aX = pt.x - QA.x, aY = pt.y - QA.y, aZ = pt.z - QA.z;
                const float bX = pt.x - QB.x, bY = pt.y - QB.y, bZ = pt.z - QB.z;
                float dA = fmaf(aX, aX, fmaf(aY, aY, aZ * aZ));
                float dB = fmaf(bX, bX, fmaf(bY, bY, bZ * bZ));
                int pA = s0 + lane, pB = s0 + lane;
                #pragma unroll
                for (int k = 2; k <= 32; k <<= 1) {
                    #pragma unroll
                    for (int j = k >> 1; j > 0; j >>= 1) {
                        const float ovA = __shfl_xor_sync(FULL, dA, j);
                        const int   oiA = __shfl_xor_sync(FULL, pA, j);
                        const float ovB = __shfl_xor_sync(FULL, dB, j);
                        const int   oiB = __shfl_xor_sync(FULL, pB, j);
                        const bool ks = ((lane & j) == 0) == ((lane & k) == 0);
                        if (ks ? (ovA < dA) : (ovA > dA)) { dA = ovA; pA = oiA; }
                        if (ks ? (ovB < dB) : (ovB > dB)) { dB = ovB; pB = oiB; }
                    }
                }
                const float dBs = __shfl_sync(FULL, dB, lane - 16);
                const int   pBs = __shfl_sync(FULL, pB, lane - 16);
                val = (lane < 16) ? dA : dBs;
                idx = (lane < 16) ? pA : pBs;
            }
            // 3 merge chunks: dual sort-32 + reversed-min merge + cleanup
            #pragma unroll
            for (int cc = 1; cc < 4; cc++) {
                const int p = s0 + cc * 32 + lane;
                const float4 pt = spts[p];
                const float aX = pt.x - QA.x, aY = pt.y - QA.y, aZ = pt.z - QA.z;
                const float bX = pt.x - QB.x, bY = pt.y - QB.y, bZ = pt.z - QB.z;
                float dA = fmaf(aX, aX, fmaf(aY, aY, aZ * aZ));
                float dB = fmaf(bX, bX, fmaf(bY, bY, bZ * bZ));
                int pA = p, pB = p;
                #pragma unroll
                for (int k = 2; k <= 32; k <<= 1) {
                    #pragma unroll
                    for (int j = k >> 1; j > 0; j >>= 1) {
                        const float ovA = __shfl_xor_sync(FULL, dA, j);
                        const int   oiA = __shfl_xor_sync(FULL, pA, j);
                        const float ovB = __shfl_xor_sync(FULL, dB, j);
                        const int   oiB = __shfl_xor_sync(FULL, pB, j);
                        const bool ks = ((lane & j) == 0) == ((lane & k) == 0);
                        if (ks ? (ovA < dA) : (ovA > dA)) { dA = ovA; pA = oiA; }
                        if (ks ? (ovB < dB) : (ovB > dB)) { dB = ovB; pB = oiB; }
                    }
                }
                // candidate top-16 reversed against each half-list
                const float cA = __shfl_sync(FULL, dA, 15 - (lane & 15));
                const int   iA = __shfl_sync(FULL, pA, 15 - (lane & 15));
                const float cB = __shfl_sync(FULL, dB, 31 - lane);
                const int   iB = __shfl_sync(FULL, pB, 31 - lane);
                const float cv = (lane < 16) ? cA : cB;
                const int   ci = (lane < 16) ? iA : iB;
                if (cv < val) { val = cv; idx = ci; }
                #pragma unroll
                for (int j = 8; j > 0; j >>= 1) {
                    const float ov = __shfl_xor_sync(FULL, val, j);
                    const int   oi = __shfl_xor_sync(FULL, idx, j);
                    const bool ks = ((lane & j) == 0);
                    if (ks ? (ov < val) : (ov > val)) { val = ov; idx = oi; }
                }
            }
            thA = __shfl_sync(FULL, val, K - 1);
            thB = __shfl_sync(FULL, val, 16 + K - 1);
        }

        // ---- main scan: 64-pt chunks, both queries, rare serial inserts ----
        auto scan_raw = [&](int s, int e) {
            for (int p0 = s; p0 < e; p0 += 64) {
                const int q0 = p0 + lane, q1 = p0 + lane + 32;
                float dA0 = FLT_MAX, dA1 = FLT_MAX, dB0 = FLT_MAX, dB1 = FLT_MAX;
                if (q0 < e) {
                    const float4 pt = spts[q0];
                    const float aX = pt.x - QA.x, aY = pt.y - QA.y, aZ = pt.z - QA.z;
                    const float bX = pt.x - QB.x, bY = pt.y - QB.y, bZ = pt.z - QB.z;
                    dA0 = fmaf(aX, aX, fmaf(aY, aY, aZ * aZ));
                    dB0 = fmaf(bX, bX, fmaf(bY, bY, bZ * bZ));
                }
                if (q1 < e) {
                    const float4 pt = spts[q1];
                    const float aX = pt.x - QA.x, aY = pt.y - QA.y, aZ = pt.z - QA.z;
                    const float bX = pt.x - QB.x, bY = pt.y - QB.y, bZ = pt.z - QB.z;
                    dA1 = fmaf(aX, aX, fmaf(aY, aY, aZ * aZ));
                    dB1 = fmaf(bX, bX, fmaf(bY, bY, bZ * bZ));
                }
                const bool cc = (fminf(dA0, dA1) < thA) | (fminf(dB0, dB1) < thB);
                if (__any_sync(FULL, cc)) {
                    topk_insert(dA0, q0, lane, val, idx, thA, 0);
                    topk_insert(dA1, q1, lane, val, idx, thA, 0);
                    topk_insert(dB0, q0, lane, val, idx, thB, 16);
                    topk_insert(dB1, q1, lane, val, idx, thB, 16);
                }
            }
        };
        // range minus the seed block [s0, s0+128)
        auto scan_range = [&](int s, int e) {
            scan_raw(s, min(e, s0));
            scan_raw(max(s, s0 + 128), e);
        };

        scan_range(cst[h], cst[h + 1]);   // home bin
        for (int l = h - 1; l >= 0; l--) {          // left expansion
            const float edge = XLO + (l + 1) * XW;
            const float gA = QA.x - edge - EPSP;
            const float gB = QB.x - edge - EPSP;
            const bool stopA = (gA > 0.0f) && (gA * gA >= thA);
            const bool stopB = (gB > 0.0f) && (gB * gB >= thB);
            if (stopA && stopB) break;
            scan_range(cst[l], cst[l + 1]);
        }
        for (int r = h + 1; r < NB; r++) {          // right expansion
            const float edge = XLO + r * XW;
            const float gA = edge - QA.x - EPSP;
            const float gB = edge - QB.x - EPSP;
            const bool stopA = (gA > 0.0f) && (gA * gA >= thA);
            const bool stopB = (gB > 0.0f) && (gB * gB >= thB);
            if (stopA && stopB) break;
            scan_range(cst[r], cst[r + 1]);
        }

        // ---- softmax per half-warp ----
        const int base = lane & 16;
        const float s_min = __shfl_sync(FULL, val, base);
        const float e = __expf(-(val - s_min) * inv_sigma);
        float esum = e;
        #pragma unroll
        for (int o = 8; o; o >>= 1) esum += __shfl_xor_sync(FULL, esum, o);
        const float w = e / esum;

        // ---- projected points ----
        const float4 gp = spts[idx];
        float wx = w * gp.x, wy = w * gp.y, wz = w * gp.z;
        #pragma unroll
        for (int o = 8; o; o >>= 1) {
            wx += __shfl_xor_sync(FULL, wx, o);
            wy += __shfl_xor_sync(FULL, wy, o);
            wz += __shfl_xor_sync(FULL, wz, o);
        }
        if (lane == 0) {
            out_pts[mA]         = wx;
            out_pts[M + mA]     = wy;
            out_pts[2 * M + mA] = wz;
        } else if (lane == 16) {
            out_pts[mB]         = wx;
            out_pts[M + mB]     = wy;
            out_pts[2 * M + mB] = wz;
        }

        // ---- features: stage (w, idx) in smem, broadcast-read (no shfl chain)
        const int og = __float_as_int(gp.w);
        mysw[lane] = w;
        mysi[lane] = og;
        __syncwarp();
        float a0 = 0.f, a1 = 0.f, c0 = 0.f, c1 = 0.f;
        #pragma unroll
        for (int j = 0; j < K; j++) {
            const float wj = mysw[j];
            const int   gj = mysi[j];
            const float2 f2 = *reinterpret_cast<const float2*>(
                featb + (size_t)gj * F + lane * 2);
            a0 = fmaf(wj, f2.x, a0);
            a1 = fmaf(wj, f2.y, a1);
        }
        #pragma unroll
        for (int j = 16; j < 16 + K; j++) {
            const float wj = mysw[j];
            const int   gj = mysi[j];
            const float2 f2 = *reinterpret_cast<const float2*>(
                featb + (size_t)gj * F + lane * 2);
            c0 = fmaf(wj, f2.x, c0);
            c1 = fmaf(wj, f2.y, c1);
        }
        __syncwarp();
        out_feat[(size_t)(2 * lane) * M + mA]     = a0;
        out_feat[(size_t)(2 * lane + 1) * M + mA] = a1;
        out_feat[(size_t)(2 * lane) * M + mB]     = c0;
        out_feat[(size_t)(2 * lane + 1) * M + mB] = c1;
    }
}

// ---------------------------------------------------------------------------
extern "C" void kernel_launch(void* const* d_in, const int* in_sizes, int n_in,
                              void* d_out, int out_size) {
    const float* pc   = (const float*)d_in[0];  // (B,3,N)
    const float* qc   = (const float*)d_in[1];  // (B,3,M)
    const float* pf   = (const float*)d_in[2];  // (B,F,N)
    const float* temp = (const float*)d_in[3];  // scalar
    float* out = (float*)d_out;                 // (B,3,M) ++ (B,F,M)
    (void)in_sizes; (void)n_in; (void)out_size;

    const int smem = N * (int)sizeof(float4) + 512 + 4 + 8192;
    cudaFuncSetAttribute(soft_projection_query,
                         cudaFuncAttributeMaxDynamicSharedMemorySize, smem);

    build_kernel<<<2 * B, 1024>>>(pc, qc);
    transpose_feat_kernel<<<dim3(N / 32, F / 32, B), dim3(32, 8)>>>(pf);
    soft_projection_query<<<dim3(37, B), 1024, smem>>>(temp, out);
}